// round 8
// baseline (speedup 1.0000x reference)
#include <cuda_runtime.h>
#include <cuda_fp16.h>
#include <math.h>
#include <stdint.h>

// Problem constants
#define Tn 512
#define Bn 8
#define En 1024
#define Hn 1024
#define Dn 512
#define Vn 32000
#define MROWS (Tn * Bn)   // 4096

// ---------------- scratch (device globals; no allocations allowed) ----------
__device__ float g_R0pre[MROWS * Dn];
__device__ float g_R1pre[MROWS * Dn];
__device__ float g_Hpre[MROWS * Hn];
__device__ float g_H[MROWS * Hn];
__device__ float g_rs[2 * Bn * 1024];     // rolling r state, [parity][b][r0|r1]
__device__ unsigned g_cnt[4];
__device__ unsigned g_done[4];

// fp16 operands
__device__ __half g_Xh[(size_t)MROWS * En];
__device__ __half g_Wxh[(size_t)Hn * En];
__device__ __half g_Win0h[(size_t)Dn * En];
__device__ __half g_Win1h[(size_t)Dn * En];
__device__ __half g_Wh[(size_t)Vn * Hn];
__device__ __half g_Hh[(size_t)MROWS * Hn];

// ================= portable PTX helpers (sm_80+) ============================
__device__ __forceinline__ uint32_t smem_u32(const void* p) {
    uint32_t a;
    asm("{ .reg .u64 t; cvta.to.shared.u64 t, %1; cvt.u32.u64 %0, t; }" : "=r"(a) : "l"(p));
    return a;
}
__device__ __forceinline__ void cp_async16(uint32_t saddr, const void* gaddr) {
    asm volatile("cp.async.cg.shared.global [%0], [%1], 16;" :: "r"(saddr), "l"(gaddr));
}
#define CP_COMMIT() asm volatile("cp.async.commit_group;" ::: "memory")
#define CP_WAIT(N)  asm volatile("cp.async.wait_group %0;" :: "n"(N) : "memory")

__device__ __forceinline__ void ldsm_x4(uint32_t& r0, uint32_t& r1, uint32_t& r2,
                                        uint32_t& r3, uint32_t addr) {
    asm volatile("ldmatrix.sync.aligned.m8n8.x4.shared.b16 {%0,%1,%2,%3}, [%4];"
                 : "=r"(r0), "=r"(r1), "=r"(r2), "=r"(r3) : "r"(addr));
}
__device__ __forceinline__ void mma16816h(float* c, const uint32_t* a, const uint32_t* b) {
    asm volatile(
        "mma.sync.aligned.m16n8k16.row.col.f32.f16.f16.f32 "
        "{%0,%1,%2,%3}, {%4,%5,%6,%7}, {%8,%9}, {%0,%1,%2,%3};"
        : "+f"(c[0]), "+f"(c[1]), "+f"(c[2]), "+f"(c[3])
        : "r"(a[0]), "r"(a[1]), "r"(a[2]), "r"(a[3]), "r"(b[0]), "r"(b[1]));
}

// ---------------- embedding gather -> fp16 X -------------------------------
__global__ void embed_h(const int* __restrict__ ids, const float* __restrict__ emb,
                        __half* __restrict__ X)
{
    int m = blockIdx.x;
    int id = __ldg(ids + m);
    float4 v = __ldg(((const float4*)(emb + (size_t)id * En)) + threadIdx.x);
    __half2* dst = (__half2*)(X + (size_t)m * En) + threadIdx.x * 2;
    dst[0] = __floats2half2_rn(v.x, v.y);
    dst[1] = __floats2half2_rn(v.z, v.w);
}

// ---------------- fp32 -> fp16 contiguous conversion --------------------------
__global__ void cvt_h_kernel(const float* __restrict__ src,
                             __half* __restrict__ dst, int n4)
{
    int i = blockIdx.x * blockDim.x + threadIdx.x;
    if (i >= n4) return;
    float4 v = ((const float4*)src)[i];
    __half2* dp = (__half2*)dst;
    dp[i * 2 + 0] = __floats2half2_rn(v.x, v.y);
    dp[i * 2 + 1] = __floats2half2_rn(v.z, v.w);
}

// ---------------- unified fp16 NT GEMM on mma.sync ---------------------------
#define KCH 64
#define TILEB (128 * KCH * 2)
#define STAGEB (2 * TILEB)

__global__ void __launch_bounds__(256, 2)
gemm16(const __half* __restrict__ A, const __half* __restrict__ W,
       const float* __restrict__ bias, float* __restrict__ C,
       const __half* __restrict__ W1, float* __restrict__ C1,
       int M, int N, int K, int lda, int flags)
{
    extern __shared__ __align__(16) char sm[];
    uint32_t sbase = smem_u32(sm);

    if (blockIdx.z) { W = W1; C = C1; }

    int tid = threadIdx.x, lane = tid & 31, wid = tid >> 5;
    int wm = wid >> 2, wn = wid & 3;
    int m0 = blockIdx.x * 128, n0 = blockIdx.y * 128;

    const __half* gA = A + (size_t)m0 * lda;
    const __half* gB = W + (size_t)n0 * K;

    float acc[4][4][4];
#pragma unroll
    for (int a = 0; a < 4; a++)
#pragma unroll
        for (int b = 0; b < 4; b++)
#pragma unroll
            for (int cx = 0; cx < 4; cx++) acc[a][b][cx] = 0.f;

    auto issue_stage = [&](int s, int kc) {
        uint32_t stb = sbase + s * STAGEB;
        const __half* ga = gA + kc * KCH;
#pragma unroll
        for (int i = 0; i < 4; ++i) {
            int q = tid + i * 256;
            int r = q >> 3, c = q & 7;
            uint32_t sa = stb + ((r >> 3) << 10) + ((r & 7) << 7) + ((c ^ (r & 7)) << 4);
            cp_async16(sa, ga + (size_t)r * lda + c * 8);
        }
        const __half* gb = gB + kc * KCH;
        uint32_t tb = stb + TILEB;
#pragma unroll
        for (int i = 0; i < 4; ++i) {
            int q = tid + i * 256;
            int r = q >> 3, c = q & 7;
            uint32_t sa = tb + ((r >> 3) << 10) + ((r & 7) << 7) + ((c ^ (r & 7)) << 4);
            cp_async16(sa, gb + (size_t)r * K + c * 8);
        }
    };

    issue_stage(0, 0);
    CP_COMMIT();

    const int NKC = K / KCH;
    for (int kc = 0; kc < NKC; ++kc) {
        if (kc + 1 < NKC) {
            issue_stage((kc + 1) & 1, kc + 1);
            CP_COMMIT();
            CP_WAIT(1);
        } else {
            CP_WAIT(0);
        }
        __syncthreads();

        uint32_t sA = sbase + (kc & 1) * STAGEB;
        uint32_t sB = sA + TILEB;

#pragma unroll
        for (int ks = 0; ks < KCH / 16; ++ks) {
            uint32_t ah[4][4], bh[4][2];

            int ra = (lane & 7) + ((lane >> 3) & 1) * 8;
            int ca = ks * 2 + ((lane >> 4) & 1);
#pragma unroll
            for (int mt = 0; mt < 4; ++mt) {
                int row = wm * 64 + mt * 16 + ra;
                uint32_t off = ((row >> 3) << 10) + ((row & 7) << 7)
                             + (((ca ^ (row & 7)) & 7) << 4);
                ldsm_x4(ah[mt][0], ah[mt][1], ah[mt][2], ah[mt][3], sA + off);
            }
            int rb = (lane & 7) + ((lane >> 4) & 1) * 8;
            int cb = ks * 2 + ((lane >> 3) & 1);
#pragma unroll
            for (int np = 0; np < 2; ++np) {
                int row = wn * 32 + np * 16 + rb;
                uint32_t off = ((row >> 3) << 10) + ((row & 7) << 7)
                             + (((cb ^ (row & 7)) & 7) << 4);
                ldsm_x4(bh[np * 2][0], bh[np * 2][1],
                        bh[np * 2 + 1][0], bh[np * 2 + 1][1], sB + off);
            }

#pragma unroll
            for (int mt = 0; mt < 4; ++mt)
#pragma unroll
                for (int nt = 0; nt < 4; ++nt)
                    mma16816h(acc[mt][nt], ah[mt], bh[nt]);
        }
        __syncthreads();
    }

#pragma unroll
    for (int mt = 0; mt < 4; ++mt) {
        int r0 = m0 + wm * 64 + mt * 16 + (lane >> 2);
#pragma unroll
        for (int nt = 0; nt < 4; ++nt) {
            int cc = n0 + wn * 32 + nt * 8 + (lane & 3) * 2;
            float bx = 0.f, by = 0.f;
            if (flags & 1) { float2 bia = *(const float2*)(bias + cc); bx = bia.x; by = bia.y; }
            float* p0 = C + (size_t)r0 * N + cc;
            float* p1 = C + (size_t)(r0 + 8) * N + cc;
            *(float2*)p0 = make_float2(acc[mt][nt][0] + bx, acc[mt][nt][1] + by);
            *(float2*)p1 = make_float2(acc[mt][nt][2] + bx, acc[mt][nt][3] + by);
        }
    }
}

// ---------------- grid barrier ------------------------------------------------
__device__ __forceinline__ void gbar_arrive_wait(unsigned* cnt, unsigned target)
{
    if (threadIdx.x == 0) {
        __threadfence();
        atomicAdd(cnt, 1u);
        while (*(volatile unsigned*)cnt < target) __nanosleep(32);
        __threadfence();
    }
    __syncthreads();
}

__device__ __forceinline__ void gbar_reset(unsigned* cnt, unsigned* done, unsigned nctas)
{
    if (threadIdx.x == 0) {
        unsigned v = atomicAdd(done, 1u);
        if (v == nctas - 1u) { *done = 0u; *cnt = 0u; __threadfence(); }
    }
}

// ---------------- fused scan: r-pipeline + h-pipeline (h lags 1 step) --------
// CTA c (of 128) owns 8 r-cols (reservoir c>>6, local cols (c&63)*8..+8)
// and 8 h-cols (c*8..+8). Steps g=0..512:
//   r-phase (g<512):  r(g) = 0.5 r(g-1) + 0.5 tanh(pre_r(g) + Wres·r(g-1))
//   h-phase (g>=1):   h(g-1) = tanh(pre_x(g-1) + [U0|U1|Wh]·[r0(g-1);r1(g-1);h(g-2)])
// One grid barrier per step; r state double-buffered by parity; h read/written
// in the trajectory array (distinct t-slots, no conflict).
__global__ void __launch_bounds__(256)
fused_scan(const float* __restrict__ pre0, const float* __restrict__ pre1,
           const float* __restrict__ Wr0, const float* __restrict__ Wr1,
           const float* __restrict__ U0, const float* __restrict__ U1,
           const float* __restrict__ Whw, const float* __restrict__ Hpre,
           float* __restrict__ H, __half* __restrict__ Hh)
{
    extern __shared__ __align__(16) float smem[];
    float* sWr  = smem;                    // 8*512
    float* sWh  = sWr + 8 * 512;           // 8*2048
    float* sRst = sWh + 8 * 2048;          // 8*512
    float* sHst = sRst + 8 * 512;          // 8*2048

    int cta = blockIdx.x;
    int res = cta >> 6;
    int jr0 = (cta & 63) * 8;
    int jh0 = cta * 8;
    const float* pre = res ? pre1 : pre0;
    const float* Wr  = res ? Wr1 : Wr0;

    int tid = threadIdx.x, lane = tid & 31, b = tid >> 5;

    // weights (once): r rows
    for (int i = tid; i < 8 * Dn / 4; i += 256)
        ((float4*)sWr)[i] = ((const float4*)(Wr + (size_t)jr0 * Dn))[i];
    // h rows: [U0 | U1 | Wh] per row (512+512+1024 floats)
    for (int idx = tid; idx < 8 * 2048 / 4; idx += 256) {
        int row = idx >> 9, c4 = idx & 511;
        int j = jh0 + row;
        float4 v;
        if (c4 < 128)       v = ((const float4*)(U0 + (size_t)j * Dn))[c4];
        else if (c4 < 256)  v = ((const float4*)(U1 + (size_t)j * Dn))[c4 - 128];
        else                v = ((const float4*)(Whw + (size_t)j * Hn))[c4 - 256];
        ((float4*)sWh)[idx] = v;
    }
    __syncthreads();

    unsigned* cnt = &g_cnt[0];
    const float4* rs4 = (const float4*)g_rs;   // [2][Bn][256] float4
    const float4* H4 = (const float4*)H;

    for (int g = 0; g <= Tn; ++g) {
        // ---- state loads
        if (g < Tn) {
            if (g == 0) {
                float4 z = make_float4(0.f, 0.f, 0.f, 0.f);
                for (int i = tid; i < 8 * Dn / 4; i += 256) ((float4*)sRst)[i] = z;
            } else {
                int p = (g - 1) & 1;
                for (int i = tid; i < 8 * Dn / 4; i += 256) {
                    int bb = i >> 7, c = i & 127;
                    ((float4*)sRst)[i] = rs4[(p * Bn + bb) * 256 + res * 128 + c];
                }
            }
        }
        if (g >= 1) {
            int p = (g - 1) & 1;
            for (int i = tid; i < 8 * 2048 / 4; i += 256) {
                int bb = i >> 9, c4 = i & 511;
                float4 v;
                if (c4 < 256) v = rs4[(p * Bn + bb) * 256 + c4];
                else if (g >= 2) v = H4[((size_t)bb * Tn + (g - 2)) * 256 + (c4 - 256)];
                else v = make_float4(0.f, 0.f, 0.f, 0.f);
                ((float4*)sHst)[i] = v;
            }
        }
        __syncthreads();

        // ---- r-phase
        if (g < Tn) {
            const float4* rb = (const float4*)(sRst + b * Dn);
            float4 rv[4];
#pragma unroll
            for (int i = 0; i < 4; i++) rv[i] = rb[i * 32 + lane];
            float myout = 0.f;
#pragma unroll
            for (int jj = 0; jj < 8; ++jj) {
                const float4* wr = (const float4*)(sWr + jj * Dn);
                float sv = 0.f;
#pragma unroll
                for (int i = 0; i < 4; i++) {
                    float4 w4 = wr[i * 32 + lane];
                    sv += rv[i].x * w4.x + rv[i].y * w4.y + rv[i].z * w4.z + rv[i].w * w4.w;
                }
#pragma unroll
                for (int off = 16; off; off >>= 1) sv += __shfl_xor_sync(0xffffffffu, sv, off);
                if (lane == jj) myout = sv;
            }
            if (lane < 8) {
                int jl = jr0 + lane;
                float rold = sRst[b * Dn + jl];
                float pr = __ldcg(pre + ((size_t)b * Tn + g) * Dn + jl);
                g_rs[((g & 1) * Bn + b) * 1024 + res * Dn + jl] =
                    0.5f * rold + 0.5f * tanhf(pr + myout);
            }
        }

        // ---- h-phase (computes h at t = g-1)
        if (g >= 1) {
            const float4* hb = (const float4*)(sHst + b * 2048);
            float4 hv[16];
#pragma unroll
            for (int i = 0; i < 16; i++) hv[i] = hb[i * 32 + lane];
            float myout = 0.f;
#pragma unroll
            for (int jj = 0; jj < 8; ++jj) {
                const float4* wr = (const float4*)(sWh + jj * 2048);
                float sv = 0.f;
#pragma unroll
                for (int i = 0; i < 16; i++) {
                    float4 w4 = wr[i * 32 + lane];
                    sv += hv[i].x * w4.x + hv[i].y * w4.y + hv[i].z * w4.z + hv[i].w * w4.w;
                }
#pragma unroll
                for (int off = 16; off; off >>= 1) sv += __shfl_xor_sync(0xffffffffu, sv, off);
                if (lane == jj) myout = sv;
            }
            if (lane < 8) {
                int j = jh0 + lane;
                size_t row = (size_t)b * Tn + (g - 1);
                float val = tanhf(__ldcg(Hpre + row * Hn + j) + myout);
                H[row * Hn + j] = val;
                Hh[row * Hn + j] = __float2half(val);
            }
        }
        __syncthreads();
        gbar_arrive_wait(cnt, 128u * (unsigned)(g + 1));
    }
    gbar_reset(cnt, &g_done[0], 128u);
}

// ---------------- launch ------------------------------------------------------
extern "C" void kernel_launch(void* const* d_in, const int* in_sizes, int n_in,
                              void* d_out, int out_size)
{
    const int*   ids   = (const int*)  d_in[0];
    const float* emb   = (const float*)d_in[1];
    const float* W_x   = (const float*)d_in[2];
    const float* W_h   = (const float*)d_in[3];
    const float* b_h   = (const float*)d_in[4];
    const float* Win0  = (const float*)d_in[5];
    const float* Wres0 = (const float*)d_in[6];
    const float* U0    = (const float*)d_in[7];
    const float* Win1  = (const float*)d_in[8];
    const float* Wres1 = (const float*)d_in[9];
    const float* U1    = (const float*)d_in[10];
    const float* outW  = (const float*)d_in[11];
    const float* outb  = (const float*)d_in[12];
    float* out = (float*)d_out;

    float *R0pre, *R1pre, *Hpre, *Hst;
    __half *Xh, *Wxh, *Win0h, *Win1h, *Wh16, *Hh16;
    cudaGetSymbolAddress((void**)&R0pre, g_R0pre);
    cudaGetSymbolAddress((void**)&R1pre, g_R1pre);
    cudaGetSymbolAddress((void**)&Hpre,  g_Hpre);
    cudaGetSymbolAddress((void**)&Hst,   g_H);
    cudaGetSymbolAddress((void**)&Xh,    g_Xh);
    cudaGetSymbolAddress((void**)&Wxh,   g_Wxh);
    cudaGetSymbolAddress((void**)&Win0h, g_Win0h);
    cudaGetSymbolAddress((void**)&Win1h, g_Win1h);
    cudaGetSymbolAddress((void**)&Wh16,  g_Wh);
    cudaGetSymbolAddress((void**)&Hh16,  g_Hh);

    cudaFuncSetAttribute(fused_scan,
                         cudaFuncAttributeMaxDynamicSharedMemorySize, 163840);
    cudaFuncSetAttribute(gemm16,
                         cudaFuncAttributeMaxDynamicSharedMemorySize, 2 * STAGEB);

    // 1) gathers + weight conversions
    embed_h<<<MROWS, 256>>>(ids, emb, Xh);
    cvt_h_kernel<<<(Dn * En / 4 + 255) / 256, 256>>>(Win0, Win0h, Dn * En / 4);
    cvt_h_kernel<<<(Dn * En / 4 + 255) / 256, 256>>>(Win1, Win1h, Dn * En / 4);
    cvt_h_kernel<<<(Hn * En / 4 + 255) / 256, 256>>>(W_x, Wxh, Hn * En / 4);
    cvt_h_kernel<<<(Vn * Hn / 4 + 255) / 256, 256>>>(outW, Wh16, Vn * Hn / 4);

    // 2) reservoir input projections (dual via z) + x-part of Hpre
    gemm16<<<dim3(MROWS / 128, Dn / 128, 2), 256, 2 * STAGEB>>>(
        Xh, Win0h, nullptr, R0pre, Win1h, R1pre, MROWS, Dn, En, En, 0);
    gemm16<<<dim3(MROWS / 128, Hn / 128, 1), 256, 2 * STAGEB>>>(
        Xh, Wxh, b_h, Hpre, nullptr, nullptr, MROWS, Hn, En, En, 1);

    // 3) fused pipelined scans (r + lagged h, one barrier per step)
    fused_scan<<<128, 256, 163840>>>(R0pre, R1pre, Wres0, Wres1,
                                     U0, U1, W_h, Hpre, Hst, Hh16);

    // 4) logits GEMM + bias (fp16 MMA)
    gemm16<<<dim3(MROWS / 128, Vn / 128, 1), 256, 2 * STAGEB>>>(
        Hh16, Wh16, outb, out, nullptr, nullptr, MROWS, Vn, Hn, Hn, 1);
}

// round 9
// speedup vs baseline: 1.0997x; 1.0997x over previous
#include <cuda_runtime.h>
#include <cuda_fp16.h>
#include <math.h>
#include <stdint.h>

#define Tn 512
#define Bn 8
#define En 1024
#define Hn 1024
#define Dn 512
#define Vn 32000
#define MROWS (Tn * Bn)
#define KCAT 2048
#define NTILES ((MROWS / 128) * (Vn / 128))   // 8000
#define TPC 2000

__device__ float g_R0pre[MROWS * Dn];
__device__ float g_R1pre[MROWS * Dn];
__device__ float g_R0[MROWS * Dn];
__device__ float g_R1[MROWS * Dn];
__device__ float g_Hpre[MROWS * Hn];
__device__ float g_H[MROWS * Hn];
__device__ unsigned g_cnt[4];
__device__ unsigned g_done[4];
__device__ unsigned g_prog;
__device__ unsigned g_tilectr;

__device__ __half g_Xcat[(size_t)MROWS * KCAT];
__device__ __half g_Wcat[(size_t)Hn * KCAT];
__device__ __half g_Win0h[(size_t)Dn * En];
__device__ __half g_Win1h[(size_t)Dn * En];
__device__ __half g_Wh[(size_t)Vn * Hn];
__device__ __half g_Hh[(size_t)MROWS * Hn];

__device__ __forceinline__ uint32_t smem_u32(const void* p) {
    uint32_t a;
    asm("{ .reg .u64 t; cvta.to.shared.u64 t, %1; cvt.u32.u64 %0, t; }" : "=r"(a) : "l"(p));
    return a;
}
__device__ __forceinline__ void cp_async16(uint32_t saddr, const void* gaddr) {
    asm volatile("cp.async.cg.shared.global [%0], [%1], 16;" :: "r"(saddr), "l"(gaddr));
}
#define CP_COMMIT() asm volatile("cp.async.commit_group;" ::: "memory")
#define CP_WAIT(N)  asm volatile("cp.async.wait_group %0;" :: "n"(N) : "memory")

__device__ __forceinline__ void ldsm_x4(uint32_t& r0, uint32_t& r1, uint32_t& r2,
                                        uint32_t& r3, uint32_t addr) {
    asm volatile("ldmatrix.sync.aligned.m8n8.x4.shared.b16 {%0,%1,%2,%3}, [%4];"
                 : "=r"(r0), "=r"(r1), "=r"(r2), "=r"(r3) : "r"(addr));
}
__device__ __forceinline__ void mma16816h(float* c, const uint32_t* a, const uint32_t* b) {
    asm volatile(
        "mma.sync.aligned.m16n8k16.row.col.f32.f16.f16.f32 "
        "{%0,%1,%2,%3}, {%4,%5,%6,%7}, {%8,%9}, {%0,%1,%2,%3};"
        : "+f"(c[0]), "+f"(c[1]), "+f"(c[2]), "+f"(c[3])
        : "r"(a[0]), "r"(a[1]), "r"(a[2]), "r"(a[3]), "r"(b[0]), "r"(b[1]));
}

__global__ void embed_h(const int* __restrict__ ids, const float* __restrict__ emb,
                        __half* __restrict__ Xcat)
{
    int m = blockIdx.x;
    if (m == 0 && threadIdx.x == 0) { g_prog = 0u; g_tilectr = 0u; }
    int id = __ldg(ids + m);
    float4 v = __ldg(((const float4*)(emb + (size_t)id * En)) + threadIdx.x);
    __half2* dst = (__half2*)(Xcat + (size_t)m * KCAT) + threadIdx.x * 2;
    dst[0] = __floats2half2_rn(v.x, v.y);
    dst[1] = __floats2half2_rn(v.z, v.w);
}

__global__ void cvt_h_kernel(const float* __restrict__ src,
                             __half* __restrict__ dst, int n4)
{
    int i = blockIdx.x * blockDim.x + threadIdx.x;
    if (i >= n4) return;
    float4 v = ((const float4*)src)[i];
    __half2* dp = (__half2*)dst;
    dp[i * 2 + 0] = __floats2half2_rn(v.x, v.y);
    dp[i * 2 + 1] = __floats2half2_rn(v.z, v.w);
}

__global__ void cvt_r_kernel(const float* __restrict__ R0, const float* __restrict__ R1,
                             __half* __restrict__ Xcat)
{
    int i = blockIdx.x * blockDim.x + threadIdx.x;
    int m = i >> 8;
    int col = (i & 255) * 4;
    const float* R = (col >= Dn) ? R1 : R0;
    int d = col & (Dn - 1);
    float4 v = *(const float4*)(R + (size_t)m * Dn + d);
    __half2* p = (__half2*)(Xcat + (size_t)m * KCAT + En + col);
    p[0] = __floats2half2_rn(v.x, v.y);
    p[1] = __floats2half2_rn(v.z, v.w);
}

__global__ void pack_wcat(const float* __restrict__ Wx, const float* __restrict__ U0,
                          const float* __restrict__ U1, __half* __restrict__ Wcat)
{
    int n = blockIdx.x;
    int c = threadIdx.x * 4;
    const float* src;
    if (c < En)            src = Wx + (size_t)n * En + c;
    else if (c < En + Dn)  src = U0 + (size_t)n * Dn + (c - En);
    else                   src = U1 + (size_t)n * Dn + (c - En - Dn);
    float4 v = *(const float4*)src;
    __half2* p = (__half2*)(Wcat + (size_t)n * KCAT + c);
    p[0] = __floats2half2_rn(v.x, v.y);
    p[1] = __floats2half2_rn(v.z, v.w);
}

#define KCH 64
#define TILEB (128 * KCH * 2)
#define STAGEB (2 * TILEB)

// ---- shared tile-GEMM body (device function used by gemm16 and workers) ----
__device__ __forceinline__ void gemm_tile(
    uint32_t sbase, int tid, int lane, int wm, int wn,
    const __half* gA, const __half* gB, int lda, int ldb, int K,
    const float* bias, float* C, int ldc, int m0, int n0, int flags)
{
    float acc[4][4][4];
#pragma unroll
    for (int a = 0; a < 4; a++)
#pragma unroll
        for (int bq = 0; bq < 4; bq++)
#pragma unroll
            for (int cx = 0; cx < 4; cx++) acc[a][bq][cx] = 0.f;

    auto issue_stage = [&](int s, int kc) {
        uint32_t stb = sbase + s * STAGEB;
        const __half* ga = gA + kc * KCH;
#pragma unroll
        for (int i = 0; i < 4; ++i) {
            int q = tid + i * 256;
            int r = q >> 3, c = q & 7;
            uint32_t sa = stb + ((r >> 3) << 10) + ((r & 7) << 7) + ((c ^ (r & 7)) << 4);
            cp_async16(sa, ga + (size_t)r * lda + c * 8);
        }
        const __half* gb = gB + kc * KCH;
        uint32_t tb = stb + TILEB;
#pragma unroll
        for (int i = 0; i < 4; ++i) {
            int q = tid + i * 256;
            int r = q >> 3, c = q & 7;
            uint32_t sa = tb + ((r >> 3) << 10) + ((r & 7) << 7) + ((c ^ (r & 7)) << 4);
            cp_async16(sa, gb + (size_t)r * ldb + c * 8);
        }
    };

    issue_stage(0, 0);
    CP_COMMIT();

    const int NKC = K / KCH;
    for (int kc = 0; kc < NKC; ++kc) {
        if (kc + 1 < NKC) { issue_stage((kc + 1) & 1, kc + 1); CP_COMMIT(); CP_WAIT(1); }
        else { CP_WAIT(0); }
        __syncthreads();

        uint32_t sA = sbase + (kc & 1) * STAGEB;
        uint32_t sB = sA + TILEB;

#pragma unroll
        for (int ks = 0; ks < KCH / 16; ++ks) {
            uint32_t ah[4][4], bh[4][2];
            int ra = (lane & 7) + ((lane >> 3) & 1) * 8;
            int ca = ks * 2 + ((lane >> 4) & 1);
#pragma unroll
            for (int mt = 0; mt < 4; ++mt) {
                int row = wm * 64 + mt * 16 + ra;
                uint32_t off = ((row >> 3) << 10) + ((row & 7) << 7)
                             + (((ca ^ (row & 7)) & 7) << 4);
                ldsm_x4(ah[mt][0], ah[mt][1], ah[mt][2], ah[mt][3], sA + off);
            }
            int rb = (lane & 7) + ((lane >> 4) & 1) * 8;
            int cb = ks * 2 + ((lane >> 3) & 1);
#pragma unroll
            for (int np = 0; np < 2; ++np) {
                int row = wn * 32 + np * 16 + rb;
                uint32_t off = ((row >> 3) << 10) + ((row & 7) << 7)
                             + (((cb ^ (row & 7)) & 7) << 4);
                ldsm_x4(bh[np * 2][0], bh[np * 2][1],
                        bh[np * 2 + 1][0], bh[np * 2 + 1][1], sB + off);
            }
#pragma unroll
            for (int mt = 0; mt < 4; ++mt)
#pragma unroll
                for (int nt = 0; nt < 4; ++nt)
                    mma16816h(acc[mt][nt], ah[mt], bh[nt]);
        }
        __syncthreads();
    }

#pragma unroll
    for (int mt = 0; mt < 4; ++mt) {
        int r0 = m0 + wm * 64 + mt * 16 + (lane >> 2);
#pragma unroll
        for (int nt = 0; nt < 4; ++nt) {
            int cc = n0 + wn * 32 + nt * 8 + (lane & 3) * 2;
            float bx = 0.f, by = 0.f;
            if (flags & 1) { float2 bia = *(const float2*)(bias + cc); bx = bia.x; by = bia.y; }
            float* p0 = C + (size_t)r0 * ldc + cc;
            float* p1 = C + (size_t)(r0 + 8) * ldc + cc;
            *(float2*)p0 = make_float2(acc[mt][nt][0] + bx, acc[mt][nt][1] + by);
            *(float2*)p1 = make_float2(acc[mt][nt][2] + bx, acc[mt][nt][3] + by);
        }
    }
}

__global__ void __launch_bounds__(256, 2)
gemm16(const __half* __restrict__ A, const __half* __restrict__ W,
       const float* __restrict__ bias, float* __restrict__ C,
       const __half* __restrict__ W1, float* __restrict__ C1,
       int M, int N, int K, int lda, int flags)
{
    extern __shared__ __align__(16) char sm[];
    uint32_t sbase = smem_u32(sm);
    if (blockIdx.z) { W = W1; C = C1; }
    int tid = threadIdx.x, lane = tid & 31, wid = tid >> 5;
    gemm_tile(sbase, tid, lane, wid >> 2, wid & 3,
              A + (size_t)blockIdx.x * 128 * lda, W + (size_t)blockIdx.y * 128 * K,
              lda, K, K, bias, C, N, blockIdx.x * 128, blockIdx.y * 128, flags);
}

__device__ __forceinline__ void gbar_arrive_wait(unsigned* cnt, unsigned target)
{
    if (threadIdx.x == 0) {
        __threadfence();
        atomicAdd(cnt, 1u);
        while (*(volatile unsigned*)cnt < target) __nanosleep(32);
        __threadfence();
    }
    __syncthreads();
}
__device__ __forceinline__ void gbar_reset(unsigned* cnt, unsigned* done, unsigned nctas)
{
    if (threadIdx.x == 0) {
        unsigned v = atomicAdd(done, 1u);
        if (v == nctas - 1u) { *done = 0u; *cnt = 0u; __threadfence(); }
    }
}

__global__ void __launch_bounds__(256)
rscan_kernel(const float* __restrict__ pre0, const float* __restrict__ pre1,
             const float* __restrict__ W0, const float* __restrict__ W1,
             float* __restrict__ R0, float* __restrict__ R1)
{
    __shared__ __align__(16) float sW[8 * Dn];
    __shared__ __align__(16) float sR[Bn * Dn];

    int res  = blockIdx.x >> 6;
    int jblk = blockIdx.x & 63;
    int j0   = jblk * 8;
    const float* pre  = res ? pre1 : pre0;
    const float* Wres = res ? W1 : W0;
    float* Rout = res ? R1 : R0;
    unsigned* cnt = &g_cnt[res];

    int tid = threadIdx.x, lane = tid & 31, b = tid >> 5;

    for (int i = tid; i < 8 * Dn / 4; i += 256)
        ((float4*)sW)[i] = ((const float4*)(Wres + (size_t)j0 * Dn))[i];
    __syncthreads();

    for (int t = 0; t < Tn; ++t) {
        if (t == 0) {
            float4 z = make_float4(0.f, 0.f, 0.f, 0.f);
            for (int i = tid; i < Bn * Dn / 4; i += 256) ((float4*)sR)[i] = z;
        } else {
            for (int i = tid; i < Bn * Dn / 4; i += 256) {
                int bb = i >> 7, c = i & 127;
                ((float4*)sR)[i] =
                    __ldcg(((const float4*)(Rout + ((size_t)bb * Tn + (t - 1)) * Dn)) + c);
            }
        }
        __syncthreads();

        const float4* rb = (const float4*)(sR + b * Dn);
        float4 rv[4];
#pragma unroll
        for (int i = 0; i < 4; i++) rv[i] = rb[i * 32 + lane];

        float myout = 0.f;
#pragma unroll
        for (int jj = 0; jj < 8; ++jj) {
            const float4* wr = (const float4*)(sW + jj * Dn);
            float sv = 0.f;
#pragma unroll
            for (int i = 0; i < 4; i++) {
                float4 w4 = wr[i * 32 + lane];
                sv += rv[i].x * w4.x + rv[i].y * w4.y + rv[i].z * w4.z + rv[i].w * w4.w;
            }
#pragma unroll
            for (int off = 16; off; off >>= 1) sv += __shfl_xor_sync(0xffffffffu, sv, off);
            if (lane == jj) myout = sv;
        }
        if (lane < 8) {
            int j = j0 + lane;
            size_t row = (size_t)b * Tn + t;
            float rold = sR[b * Dn + j];
            float p = __ldcg(pre + row * Dn + j);
            Rout[row * Dn + j] = 0.5f * rold + 0.5f * tanhf(p + myout);
        }
        __syncthreads();
        gbar_arrive_wait(cnt, 64u * (unsigned)(t + 1));
    }
    gbar_reset(cnt, &g_done[res], 64u);
}

// ---------------- hscan + overlapped logits ----------------------------------
__global__ void __launch_bounds__(256, 2)
hscan_logits(const float* __restrict__ Hpre, const float* __restrict__ Wh,
             float* __restrict__ Hout, __half* __restrict__ Hh,
             const __half* __restrict__ Wlg, const float* __restrict__ bias,
             float* __restrict__ C)
{
    extern __shared__ __align__(16) char sm[];
    int bid = blockIdx.x;
    int tid = threadIdx.x, lane = tid & 31, wid = tid >> 5;

    if (bid < 128) {
        float* smem = (float*)sm;
        float* sW = smem;
        float* sH = smem + 8 * Hn;
        int b = tid >> 5;
        int j0 = bid * 8;
        unsigned* cnt = &g_cnt[2];

        for (int i = tid; i < 8 * Hn / 4; i += 256)
            ((float4*)sW)[i] = ((const float4*)(Wh + (size_t)j0 * Hn))[i];
        __syncthreads();

        for (int t = 0; t < Tn; ++t) {
            if (t == 0) {
                float4 z = make_float4(0.f, 0.f, 0.f, 0.f);
                for (int i = tid; i < Bn * Hn / 4; i += 256) ((float4*)sH)[i] = z;
            } else {
                for (int i = tid; i < Bn * Hn / 4; i += 256) {
                    int bb = i >> 8, c = i & 255;
                    ((float4*)sH)[i] =
                        __ldcg(((const float4*)(Hout + ((size_t)bb * Tn + (t - 1)) * Hn)) + c);
                }
            }
            __syncthreads();

            const float4* hb = (const float4*)(sH + b * Hn);
            float4 hv[8];
#pragma unroll
            for (int i = 0; i < 8; i++) hv[i] = hb[i * 32 + lane];

            float myout = 0.f;
#pragma unroll
            for (int jj = 0; jj < 8; ++jj) {
                const float4* wr = (const float4*)(sW + jj * Hn);
                float sv = 0.f;
#pragma unroll
                for (int i = 0; i < 8; i++) {
                    float4 w4 = wr[i * 32 + lane];
                    sv += hv[i].x * w4.x + hv[i].y * w4.y + hv[i].z * w4.z + hv[i].w * w4.w;
                }
#pragma unroll
                for (int off = 16; off; off >>= 1) sv += __shfl_xor_sync(0xffffffffu, sv, off);
                if (lane == jj) myout = sv;
            }
            if (lane < 8) {
                int j = j0 + lane;
                size_t row = (size_t)b * Tn + t;
                float val = tanhf(__ldcg(Hpre + row * Hn + j) + myout);
                Hout[row * Hn + j] = val;
                Hh[row * Hn + j] = __float2half(val);
            }
            __syncthreads();
            gbar_arrive_wait(cnt, 128u * (unsigned)(t + 1));
            if (bid == 0 && tid == 0)
                *(volatile unsigned*)&g_prog = (unsigned)(t + 1);
        }
        gbar_reset(cnt, &g_done[2], 128u);
        __syncthreads();
    }

    // worker role
    uint32_t sbase = smem_u32(sm);
    int wm = wid >> 2, wn = wid & 3;
    __shared__ unsigned s_tile;

    for (;;) {
        if (tid == 0) s_tile = atomicAdd(&g_tilectr, 1u);
        __syncthreads();
        unsigned tile = s_tile;
        __syncthreads();
        if (tile >= NTILES) break;

        int tc  = tile / TPC;
        int rem = tile % TPC;
        int mi  = (rem / 250) * 4 + tc;
        int ni  = rem % 250;

        if (tid == 0) {
            unsigned need = (unsigned)(tc + 1) * 128u;
            while (*(volatile unsigned*)&g_prog < need) __nanosleep(128);
        }
        __syncthreads();
        __threadfence();

        gemm_tile(sbase, tid, lane, wm, wn,
                  Hh + (size_t)mi * 128 * Hn, Wlg + (size_t)ni * 128 * Hn,
                  Hn, Hn, Hn, bias, C, Vn, mi * 128, ni * 128, 1);
    }
}

extern "C" void kernel_launch(void* const* d_in, const int* in_sizes, int n_in,
                              void* d_out, int out_size)
{
    const int*   ids   = (const int*)  d_in[0];
    const float* emb   = (const float*)d_in[1];
    const float* W_x   = (const float*)d_in[2];
    const float* W_h   = (const float*)d_in[3];
    const float* b_h   = (const float*)d_in[4];
    const float* Win0  = (const float*)d_in[5];
    const float* Wres0 = (const float*)d_in[6];
    const float* U0    = (const float*)d_in[7];
    const float* Win1  = (const float*)d_in[8];
    const float* Wres1 = (const float*)d_in[9];
    const float* U1    = (const float*)d_in[10];
    const float* outW  = (const float*)d_in[11];
    const float* outb  = (const float*)d_in[12];
    float* out = (float*)d_out;

    float *R0pre, *R1pre, *R0, *R1, *Hpre, *Hst;
    __half *Xcat, *Wcat, *Win0h, *Win1h, *Wh16, *Hh16;
    cudaGetSymbolAddress((void**)&R0pre, g_R0pre);
    cudaGetSymbolAddress((void**)&R1pre, g_R1pre);
    cudaGetSymbolAddress((void**)&R0,    g_R0);
    cudaGetSymbolAddress((void**)&R1,    g_R1);
    cudaGetSymbolAddress((void**)&Hpre,  g_Hpre);
    cudaGetSymbolAddress((void**)&Hst,   g_H);
    cudaGetSymbolAddress((void**)&Xcat,  g_Xcat);
    cudaGetSymbolAddress((void**)&Wcat,  g_Wcat);
    cudaGetSymbolAddress((void**)&Win0h, g_Win0h);
    cudaGetSymbolAddress((void**)&Win1h, g_Win1h);
    cudaGetSymbolAddress((void**)&Wh16,  g_Wh);
    cudaGetSymbolAddress((void**)&Hh16,  g_Hh);

    cudaFuncSetAttribute(gemm16,
                         cudaFuncAttributeMaxDynamicSharedMemorySize, 2 * STAGEB);
    cudaFuncSetAttribute(hscan_logits,
                         cudaFuncAttributeMaxDynamicSharedMemorySize, 2 * STAGEB);

    // 1) gathers + weight conversions (embed also resets g_prog / g_tilectr)
    embed_h<<<MROWS, 256>>>(ids, emb, Xcat);
    cvt_h_kernel<<<(Dn * En / 4 + 255) / 256, 256>>>(Win0, Win0h, Dn * En / 4);
    cvt_h_kernel<<<(Dn * En / 4 + 255) / 256, 256>>>(Win1, Win1h, Dn * En / 4);
    pack_wcat<<<Hn, 512>>>(W_x, U0, U1, Wcat);
    cvt_h_kernel<<<(Vn * Hn / 4 + 255) / 256, 256>>>(outW, Wh16, Vn * Hn / 4);

    // 2) reservoir input projections (dual via z)
    gemm16<<<dim3(MROWS / 128, Dn / 128, 2), 256, 2 * STAGEB>>>(
        Xcat, Win0h, nullptr, R0pre, Win1h, R1pre, MROWS, Dn, En, KCAT, 0);

    // 3) sequential reservoir scans
    rscan_kernel<<<128, 256>>>(R0pre, R1pre, Wres0, Wres1, R0, R1);

    // 4) R -> fp16 into Xcat tail; Hpre = [X|R0|R1] @ [W_x|U0|U1]^T + b_h
    cvt_r_kernel<<<MROWS * (2 * Dn) / 4 / 256, 256>>>(R0, R1, Xcat);
    gemm16<<<dim3(MROWS / 128, Hn / 128, 1), 256, 2 * STAGEB>>>(
        Xcat, Wcat, b_h, Hpre, nullptr, nullptr, MROWS, Hn, KCAT, KCAT, 1);

    // 5) hidden scan + overlapped logits (one kernel, 296 CTAs)
    hscan_logits<<<296, 256, 2 * STAGEB>>>(Hpre, W_h, Hst, Hh16, Wh16, outb, out);
}

// round 10
// speedup vs baseline: 1.3780x; 1.2531x over previous
#include <cuda_runtime.h>
#include <cuda_fp16.h>
#include <math.h>
#include <stdint.h>

#define Tn 512
#define Bn 8
#define En 1024
#define Hn 1024
#define Dn 512
#define Vn 32000
#define MROWS (Tn * Bn)
#define KCAT 2048
#define NTILES ((MROWS / 128) * (Vn / 128))   // 8000
#define TPC 2000
#define NUTILES 256                            // Hpre U-accumulate tiles

__device__ float g_R0pre[MROWS * Dn];
__device__ float g_R1pre[MROWS * Dn];
__device__ float g_R0[MROWS * Dn];
__device__ float g_R1[MROWS * Dn];
__device__ float g_Hpre[MROWS * Hn];
__device__ float g_H[MROWS * Hn];
__device__ unsigned g_cnt[4];
__device__ unsigned g_done[4];
__device__ unsigned g_prog_r;     // rscan progress
__device__ unsigned g_prog;       // hscan progress
__device__ unsigned g_uctr;       // U-tile queue
__device__ unsigned g_udone[4];   // U-tiles completed per t-chunk
__device__ unsigned g_tilectr;    // logits tile queue

__device__ __half g_Xcat[(size_t)MROWS * KCAT];   // [X | R0 | R1] fp16
__device__ __half g_Wcat[(size_t)Hn * KCAT];      // [W_x | U0 | U1] fp16
__device__ __half g_Win0h[(size_t)Dn * En];
__device__ __half g_Win1h[(size_t)Dn * En];
__device__ __half g_Wh[(size_t)Vn * Hn];
__device__ __half g_Hh[(size_t)MROWS * Hn];

__device__ __forceinline__ uint32_t smem_u32(const void* p) {
    uint32_t a;
    asm("{ .reg .u64 t; cvta.to.shared.u64 t, %1; cvt.u32.u64 %0, t; }" : "=r"(a) : "l"(p));
    return a;
}
__device__ __forceinline__ void cp_async16(uint32_t saddr, const void* gaddr) {
    asm volatile("cp.async.cg.shared.global [%0], [%1], 16;" :: "r"(saddr), "l"(gaddr));
}
#define CP_COMMIT() asm volatile("cp.async.commit_group;" ::: "memory")
#define CP_WAIT(N)  asm volatile("cp.async.wait_group %0;" :: "n"(N) : "memory")

__device__ __forceinline__ void ldsm_x4(uint32_t& r0, uint32_t& r1, uint32_t& r2,
                                        uint32_t& r3, uint32_t addr) {
    asm volatile("ldmatrix.sync.aligned.m8n8.x4.shared.b16 {%0,%1,%2,%3}, [%4];"
                 : "=r"(r0), "=r"(r1), "=r"(r2), "=r"(r3) : "r"(addr));
}
__device__ __forceinline__ void mma16816h(float* c, const uint32_t* a, const uint32_t* b) {
    asm volatile(
        "mma.sync.aligned.m16n8k16.row.col.f32.f16.f16.f32 "
        "{%0,%1,%2,%3}, {%4,%5,%6,%7}, {%8,%9}, {%0,%1,%2,%3};"
        : "+f"(c[0]), "+f"(c[1]), "+f"(c[2]), "+f"(c[3])
        : "r"(a[0]), "r"(a[1]), "r"(a[2]), "r"(a[3]), "r"(b[0]), "r"(b[1]));
}

// -------- launch 1: embedding gather + counter reset -------------------------
__global__ void embed_h(const int* __restrict__ ids, const float* __restrict__ emb,
                        __half* __restrict__ Xcat)
{
    int m = blockIdx.x;
    if (m == 0 && threadIdx.x == 0) {
        g_prog_r = 0u; g_prog = 0u; g_uctr = 0u; g_tilectr = 0u;
        g_udone[0] = g_udone[1] = g_udone[2] = g_udone[3] = 0u;
    }
    int id = __ldg(ids + m);
    float4 v = __ldg(((const float4*)(emb + (size_t)id * En)) + threadIdx.x);
    __half2* dst = (__half2*)(Xcat + (size_t)m * KCAT) + threadIdx.x * 2;
    dst[0] = __floats2half2_rn(v.x, v.y);
    dst[1] = __floats2half2_rn(v.z, v.w);
}

// -------- launch 2: Win0 + Win1 -> fp16 ---------------------------------------
__global__ void cvt_win(const float* __restrict__ Win0, const float* __restrict__ Win1,
                        __half* __restrict__ W0h, __half* __restrict__ W1h)
{
    int i = blockIdx.x * blockDim.x + threadIdx.x;
    const int n4 = Dn * En / 4;
    const float* src; __half* dst; int k;
    if (i < n4) { src = Win0; dst = W0h; k = i; }
    else        { src = Win1; dst = W1h; k = i - n4; }
    float4 v = ((const float4*)src)[k];
    __half2* dp = (__half2*)dst;
    dp[k * 2 + 0] = __floats2half2_rn(v.x, v.y);
    dp[k * 2 + 1] = __floats2half2_rn(v.z, v.w);
}

// -------- launch 3: outW -> fp16  AND  pack [W_x|U0|U1] -> Wcat ---------------
#define NB_OUTW (Vn * Hn / 4 / 256)   // 32000 blocks
__global__ void cvt_whpack(const float* __restrict__ outW, __half* __restrict__ Wh16,
                           const float* __restrict__ Wx, const float* __restrict__ U0,
                           const float* __restrict__ U1, __half* __restrict__ Wcat)
{
    if (blockIdx.x < NB_OUTW) {
        int i = blockIdx.x * 256 + threadIdx.x;
        float4 v = ((const float4*)outW)[i];
        __half2* dp = (__half2*)Wh16;
        dp[i * 2 + 0] = __floats2half2_rn(v.x, v.y);
        dp[i * 2 + 1] = __floats2half2_rn(v.z, v.w);
    } else {
        int n = blockIdx.x - NB_OUTW;          // 0..1023
#pragma unroll
        for (int h = 0; h < 2; ++h) {
            int c = (threadIdx.x + h * 256) * 4;   // 0..2044
            const float* src;
            if (c < En)            src = Wx + (size_t)n * En + c;
            else if (c < En + Dn)  src = U0 + (size_t)n * Dn + (c - En);
            else                   src = U1 + (size_t)n * Dn + (c - En - Dn);
            float4 v = *(const float4*)src;
            __half2* p = (__half2*)(Wcat + (size_t)n * KCAT + c);
            p[0] = __floats2half2_rn(v.x, v.y);
            p[1] = __floats2half2_rn(v.z, v.w);
        }
    }
}

#define KCH 64
#define TILEB (128 * KCH * 2)
#define STAGEB (2 * TILEB)

// ---- shared tile-GEMM body ---------------------------------------------------
__device__ __forceinline__ void gemm_tile(
    uint32_t sbase, int tid, int lane, int wm, int wn,
    const __half* gA, const __half* gB, int lda, int ldb, int K,
    const float* bias, float* C, int ldc, int m0, int n0, int flags)
{
    float acc[4][4][4];
#pragma unroll
    for (int a = 0; a < 4; a++)
#pragma unroll
        for (int bq = 0; bq < 4; bq++)
#pragma unroll
            for (int cx = 0; cx < 4; cx++) acc[a][bq][cx] = 0.f;

    auto issue_stage = [&](int s, int kc) {
        uint32_t stb = sbase + s * STAGEB;
        const __half* ga = gA + kc * KCH;
#pragma unroll
        for (int i = 0; i < 4; ++i) {
            int q = tid + i * 256;
            int r = q >> 3, c = q & 7;
            uint32_t sa = stb + ((r >> 3) << 10) + ((r & 7) << 7) + ((c ^ (r & 7)) << 4);
            cp_async16(sa, ga + (size_t)r * lda + c * 8);
        }
        const __half* gb = gB + kc * KCH;
        uint32_t tb = stb + TILEB;
#pragma unroll
        for (int i = 0; i < 4; ++i) {
            int q = tid + i * 256;
            int r = q >> 3, c = q & 7;
            uint32_t sa = tb + ((r >> 3) << 10) + ((r & 7) << 7) + ((c ^ (r & 7)) << 4);
            cp_async16(sa, gb + (size_t)r * ldb + c * 8);
        }
    };

    issue_stage(0, 0);
    CP_COMMIT();

    const int NKC = K / KCH;
    for (int kc = 0; kc < NKC; ++kc) {
        if (kc + 1 < NKC) { issue_stage((kc + 1) & 1, kc + 1); CP_COMMIT(); CP_WAIT(1); }
        else { CP_WAIT(0); }
        __syncthreads();

        uint32_t sA = sbase + (kc & 1) * STAGEB;
        uint32_t sB = sA + TILEB;

#pragma unroll
        for (int ks = 0; ks < KCH / 16; ++ks) {
            uint32_t ah[4][4], bh[4][2];
            int ra = (lane & 7) + ((lane >> 3) & 1) * 8;
            int ca = ks * 2 + ((lane >> 4) & 1);
#pragma unroll
            for (int mt = 0; mt < 4; ++mt) {
                int row = wm * 64 + mt * 16 + ra;
                uint32_t off = ((row >> 3) << 10) + ((row & 7) << 7)
                             + (((ca ^ (row & 7)) & 7) << 4);
                ldsm_x4(ah[mt][0], ah[mt][1], ah[mt][2], ah[mt][3], sA + off);
            }
            int rb = (lane & 7) + ((lane >> 4) & 1) * 8;
            int cb = ks * 2 + ((lane >> 3) & 1);
#pragma unroll
            for (int np = 0; np < 2; ++np) {
                int row = wn * 32 + np * 16 + rb;
                uint32_t off = ((row >> 3) << 10) + ((row & 7) << 7)
                             + (((cb ^ (row & 7)) & 7) << 4);
                ldsm_x4(bh[np * 2][0], bh[np * 2][1],
                        bh[np * 2 + 1][0], bh[np * 2 + 1][1], sB + off);
            }
#pragma unroll
            for (int mt = 0; mt < 4; ++mt)
#pragma unroll
                for (int nt = 0; nt < 4; ++nt)
                    mma16816h(acc[mt][nt], ah[mt], bh[nt]);
        }
        __syncthreads();
    }

#pragma unroll
    for (int mt = 0; mt < 4; ++mt) {
        int r0 = m0 + wm * 64 + mt * 16 + (lane >> 2);
#pragma unroll
        for (int nt = 0; nt < 4; ++nt) {
            int cc = n0 + wn * 32 + nt * 8 + (lane & 3) * 2;
            float bx = 0.f, by = 0.f;
            if (flags & 1) { float2 bia = *(const float2*)(bias + cc); bx = bia.x; by = bia.y; }
            float* p0 = C + (size_t)r0 * ldc + cc;
            float* p1 = C + (size_t)(r0 + 8) * ldc + cc;
            float2 v0 = make_float2(acc[mt][nt][0] + bx, acc[mt][nt][1] + by);
            float2 v1 = make_float2(acc[mt][nt][2] + bx, acc[mt][nt][3] + by);
            if (flags & 2) {
                float2 o0 = *(float2*)p0, o1 = *(float2*)p1;
                v0.x += o0.x; v0.y += o0.y; v1.x += o1.x; v1.y += o1.y;
            }
            *(float2*)p0 = v0;
            *(float2*)p1 = v1;
        }
    }
}

// -------- launches 4,5: standalone GEMMs --------------------------------------
__global__ void __launch_bounds__(256, 2)
gemm16(const __half* __restrict__ A, const __half* __restrict__ W,
       const float* __restrict__ bias, float* __restrict__ C,
       const __half* __restrict__ W1, float* __restrict__ C1,
       int N, int K, int lda, int ldb, int flags)
{
    extern __shared__ __align__(16) char sm[];
    uint32_t sbase = smem_u32(sm);
    if (blockIdx.z) { W = W1; C = C1; }
    int tid = threadIdx.x, lane = tid & 31, wid = tid >> 5;
    gemm_tile(sbase, tid, lane, wid >> 2, wid & 3,
              A + (size_t)blockIdx.x * 128 * lda, W + (size_t)blockIdx.y * 128 * ldb,
              lda, ldb, K, bias, C, N, blockIdx.x * 128, blockIdx.y * 128, flags);
}

__device__ __forceinline__ void gbar_arrive_wait(unsigned* cnt, unsigned target)
{
    if (threadIdx.x == 0) {
        __threadfence();
        atomicAdd(cnt, 1u);
        while (*(volatile unsigned*)cnt < target) __nanosleep(32);
        __threadfence();
    }
    __syncthreads();
}
__device__ __forceinline__ void gbar_reset(unsigned* cnt, unsigned* done, unsigned nctas)
{
    if (threadIdx.x == 0) {
        unsigned v = atomicAdd(done, 1u);
        if (v == nctas - 1u) { *done = 0u; *cnt = 0u; __threadfence(); }
    }
}

// -------- launch 6: THE mega-kernel -------------------------------------------
// 296 CTAs, 2/SM, 64KB smem. Roles:
//   bid   0-127: rscan (emits fp32 R state + fp16 into Xcat tail; g_prog_r)
//   bid 128-255: hscan (gated per t-chunk on g_udone; emits H fp32+fp16; g_prog)
//   bid 256-295: U-GEMM workers (Hpre += [R0|R1]@[U0|U1]^T), gated on g_prog_r
// All CTAs drain into the logits tile queue (gated on g_prog) afterwards.
__global__ void __launch_bounds__(256, 2)
crsd_mega(const float* __restrict__ pre0, const float* __restrict__ pre1,
          const float* __restrict__ Wr0, const float* __restrict__ Wr1,
          float* __restrict__ R0, float* __restrict__ R1,
          __half* __restrict__ Xcat, const __half* __restrict__ Wcat,
          const float* __restrict__ Hpre_c, float* __restrict__ Hpre,
          const float* __restrict__ Whw,
          float* __restrict__ Hout, __half* __restrict__ Hh,
          const __half* __restrict__ Wlg, const float* __restrict__ bias,
          float* __restrict__ C)
{
    extern __shared__ __align__(16) char sm[];
    int bid = blockIdx.x;
    int tid = threadIdx.x, lane = tid & 31, wid = tid >> 5;

    if (bid < 128) {
        // ===================== rscan role =====================
        float* smem = (float*)sm;
        float* sW = smem;                 // 8*512
        float* sR = smem + 8 * Dn;        // 8*512
        int res  = bid >> 6;
        int jblk = bid & 63;
        int j0   = jblk * 8;
        const float* pre  = res ? pre1 : pre0;
        const float* Wres = res ? Wr1 : Wr0;
        float* Rout = res ? R1 : R0;
        int b = tid >> 5;

        for (int i = tid; i < 8 * Dn / 4; i += 256)
            ((float4*)sW)[i] = ((const float4*)(Wres + (size_t)j0 * Dn))[i];
        __syncthreads();

        for (int t = 0; t < Tn; ++t) {
            if (t == 0) {
                float4 z = make_float4(0.f, 0.f, 0.f, 0.f);
                for (int i = tid; i < Bn * Dn / 4; i += 256) ((float4*)sR)[i] = z;
            } else {
                for (int i = tid; i < Bn * Dn / 4; i += 256) {
                    int bb = i >> 7, c = i & 127;
                    ((float4*)sR)[i] =
                        __ldcg(((const float4*)(Rout + ((size_t)bb * Tn + (t - 1)) * Dn)) + c);
                }
            }
            __syncthreads();

            const float4* rb = (const float4*)(sR + b * Dn);
            float4 rv[4];
#pragma unroll
            for (int i = 0; i < 4; i++) rv[i] = rb[i * 32 + lane];

            float myout = 0.f;
#pragma unroll
            for (int jj = 0; jj < 8; ++jj) {
                const float4* wr = (const float4*)(sW + jj * Dn);
                float sv = 0.f;
#pragma unroll
                for (int i = 0; i < 4; i++) {
                    float4 w4 = wr[i * 32 + lane];
                    sv += rv[i].x * w4.x + rv[i].y * w4.y + rv[i].z * w4.z + rv[i].w * w4.w;
                }
#pragma unroll
                for (int off = 16; off; off >>= 1) sv += __shfl_xor_sync(0xffffffffu, sv, off);
                if (lane == jj) myout = sv;
            }
            if (lane < 8) {
                int j = j0 + lane;
                size_t row = (size_t)b * Tn + t;
                float rold = sR[b * Dn + j];
                float p = __ldcg(pre + row * Dn + j);
                float val = 0.5f * rold + 0.5f * tanhf(p + myout);
                Rout[row * Dn + j] = val;
                Xcat[row * KCAT + En + res * Dn + j] = __float2half(val);
            }
            __syncthreads();
            gbar_arrive_wait(&g_cnt[0], 128u * (unsigned)(t + 1));
            if (bid == 0 && tid == 0)
                *(volatile unsigned*)&g_prog_r = (unsigned)(t + 1);
        }
        gbar_reset(&g_cnt[0], &g_done[0], 128u);
        __syncthreads();

    } else if (bid < 256) {
        // ===================== hscan role =====================
        float* smem = (float*)sm;
        float* sW = smem;                  // 8*1024
        float* sH = smem + 8 * Hn;         // 8*1024
        int hbid = bid - 128;
        int j0 = hbid * 8;
        int b = tid >> 5;

        for (int i = tid; i < 8 * Hn / 4; i += 256)
            ((float4*)sW)[i] = ((const float4*)(Whw + (size_t)j0 * Hn))[i];
        __syncthreads();

        for (int t = 0; t < Tn; ++t) {
            if ((t & 127) == 0) {          // gate on U-GEMM chunk completion
                if (tid == 0) {
                    int tc = t >> 7;
                    while (*(volatile unsigned*)&g_udone[tc] < 64u) __nanosleep(128);
                    __threadfence();
                }
                __syncthreads();
            }
            if (t == 0) {
                float4 z = make_float4(0.f, 0.f, 0.f, 0.f);
                for (int i = tid; i < Bn * Hn / 4; i += 256) ((float4*)sH)[i] = z;
            } else {
                for (int i = tid; i < Bn * Hn / 4; i += 256) {
                    int bb = i >> 8, c = i & 255;
                    ((float4*)sH)[i] =
                        __ldcg(((const float4*)(Hout + ((size_t)bb * Tn + (t - 1)) * Hn)) + c);
                }
            }
            __syncthreads();

            const float4* hb = (const float4*)(sH + b * Hn);
            float4 hv[8];
#pragma unroll
            for (int i = 0; i < 8; i++) hv[i] = hb[i * 32 + lane];

            float myout = 0.f;
#pragma unroll
            for (int jj = 0; jj < 8; ++jj) {
                const float4* wr = (const float4*)(sW + jj * Hn);
                float sv = 0.f;
#pragma unroll
                for (int i = 0; i < 8; i++) {
                    float4 w4 = wr[i * 32 + lane];
                    sv += hv[i].x * w4.x + hv[i].y * w4.y + hv[i].z * w4.z + hv[i].w * w4.w;
                }
#pragma unroll
                for (int off = 16; off; off >>= 1) sv += __shfl_xor_sync(0xffffffffu, sv, off);
                if (lane == jj) myout = sv;
            }
            if (lane < 8) {
                int j = j0 + lane;
                size_t row = (size_t)b * Tn + t;
                float val = tanhf(__ldcg(Hpre_c + row * Hn + j) + myout);
                Hout[row * Hn + j] = val;
                Hh[row * Hn + j] = __float2half(val);
            }
            __syncthreads();
            gbar_arrive_wait(&g_cnt[2], 128u * (unsigned)(t + 1));
            if (hbid == 0 && tid == 0)
                *(volatile unsigned*)&g_prog = (unsigned)(t + 1);
        }
        gbar_reset(&g_cnt[2], &g_done[2], 128u);
        __syncthreads();

    } else {
        // ===================== U-GEMM worker role =====================
        uint32_t sbase = smem_u32(sm);
        int wm = wid >> 2, wn = wid & 3;
        __shared__ unsigned s_ut;
        for (;;) {
            if (tid == 0) s_ut = atomicAdd(&g_uctr, 1u);
            __syncthreads();
            unsigned q = s_ut;
            __syncthreads();
            if (q >= NUTILES) break;
            int tc = q >> 6;
            int b  = (q >> 3) & 7;
            int ni = q & 7;
            int mi = b * 4 + tc;
            if (tid == 0) {
                unsigned need = (unsigned)(tc + 1) * 128u;
                while (*(volatile unsigned*)&g_prog_r < need) __nanosleep(128);
            }
            __syncthreads();
            __threadfence();
            gemm_tile(sbase, tid, lane, wm, wn,
                      Xcat + En + (size_t)mi * 128 * KCAT,
                      Wcat + En + (size_t)ni * 128 * KCAT,
                      KCAT, KCAT, 1024, nullptr, Hpre, Hn,
                      mi * 128, ni * 128, 2);
            __threadfence();
            if (tid == 0) atomicAdd(&g_udone[tc], 1u);
            __syncthreads();
        }
    }

    // ===================== logits worker (all CTAs) =====================
    uint32_t sbase = smem_u32(sm);
    int wm = wid >> 2, wn = wid & 3;
    __shared__ unsigned s_tile;
    for (;;) {
        if (tid == 0) s_tile = atomicAdd(&g_tilectr, 1u);
        __syncthreads();
        unsigned tile = s_tile;
        __syncthreads();
        if (tile >= NTILES) break;

        int tc  = tile / TPC;
        int rem = tile % TPC;
        int mi  = (rem / 250) * 4 + tc;
        int ni  = rem % 250;

        if (tid == 0) {
            unsigned need = (unsigned)(tc + 1) * 128u;
            while (*(volatile unsigned*)&g_prog < need) __nanosleep(128);
        }
        __syncthreads();
        __threadfence();

        gemm_tile(sbase, tid, lane, wm, wn,
                  Hh + (size_t)mi * 128 * Hn, Wlg + (size_t)ni * 128 * Hn,
                  Hn, Hn, Hn, bias, C, Vn, mi * 128, ni * 128, 1);
    }
}

extern "C" void kernel_launch(void* const* d_in, const int* in_sizes, int n_in,
                              void* d_out, int out_size)
{
    const int*   ids   = (const int*)  d_in[0];
    const float* emb   = (const float*)d_in[1];
    const float* W_x   = (const float*)d_in[2];
    const float* W_h   = (const float*)d_in[3];
    const float* b_h   = (const float*)d_in[4];
    const float* Win0  = (const float*)d_in[5];
    const float* Wres0 = (const float*)d_in[6];
    const float* U0    = (const float*)d_in[7];
    const float* Win1  = (const float*)d_in[8];
    const float* Wres1 = (const float*)d_in[9];
    const float* U1    = (const float*)d_in[10];
    const float* outW  = (const float*)d_in[11];
    const float* outb  = (const float*)d_in[12];
    float* out = (float*)d_out;

    float *R0pre, *R1pre, *R0, *R1, *Hpre, *Hst;
    __half *Xcat, *Wcat, *Win0h, *Win1h, *Wh16, *Hh16;
    cudaGetSymbolAddress((void**)&R0pre, g_R0pre);
    cudaGetSymbolAddress((void**)&R1pre, g_R1pre);
    cudaGetSymbolAddress((void**)&R0,    g_R0);
    cudaGetSymbolAddress((void**)&R1,    g_R1);
    cudaGetSymbolAddress((void**)&Hpre,  g_Hpre);
    cudaGetSymbolAddress((void**)&Hst,   g_H);
    cudaGetSymbolAddress((void**)&Xcat,  g_Xcat);
    cudaGetSymbolAddress((void**)&Wcat,  g_Wcat);
    cudaGetSymbolAddress((void**)&Win0h, g_Win0h);
    cudaGetSymbolAddress((void**)&Win1h, g_Win1h);
    cudaGetSymbolAddress((void**)&Wh16,  g_Wh);
    cudaGetSymbolAddress((void**)&Hh16,  g_Hh);

    cudaFuncSetAttribute(gemm16,
                         cudaFuncAttributeMaxDynamicSharedMemorySize, 2 * STAGEB);
    cudaFuncSetAttribute(crsd_mega,
                         cudaFuncAttributeMaxDynamicSharedMemorySize, 2 * STAGEB);

    // (1) embedding gather + counter reset
    embed_h<<<MROWS, 256>>>(ids, emb, Xcat);

    // (2) Win0/Win1 -> fp16
    cvt_win<<<2 * (Dn * En / 4) / 256, 256>>>(Win0, Win1, Win0h, Win1h);

    // (3) outW -> fp16  +  pack [W_x|U0|U1] -> Wcat
    cvt_whpack<<<NB_OUTW + Hn, 256>>>(outW, Wh16, W_x, U0, U1, Wcat);

    // (4) reservoir input projections (dual via z), K=1024 over Xcat x-part
    gemm16<<<dim3(MROWS / 128, Dn / 128, 2), 256, 2 * STAGEB>>>(
        Xcat, Win0h, nullptr, R0pre, Win1h, R1pre, Dn, En, KCAT, En, 0);

    // (5) Hpre_x = X @ W_x^T + b_h   (K=1024 over x-parts of Xcat/Wcat)
    gemm16<<<dim3(MROWS / 128, Hn / 128, 1), 256, 2 * STAGEB>>>(
        Xcat, Wcat, b_h, Hpre, nullptr, nullptr, Hn, En, KCAT, KCAT, 1);

    // (6) mega-kernel: rscan || U-GEMM || hscan || logits (pipelined)
    crsd_mega<<<296, 256, 2 * STAGEB>>>(
        R0pre, R1pre, Wres0, Wres1, R0, R1, Xcat, Wcat,
        Hpre, Hpre, W_h, Hst, Hh16, Wh16, outb, out);
}

// round 11
// speedup vs baseline: 1.4823x; 1.0757x over previous
#include <cuda_runtime.h>
#include <cuda_fp16.h>
#include <math.h>
#include <stdint.h>

#define Tn 512
#define Bn 8
#define En 1024
#define Hn 1024
#define Dn 512
#define Vn 32000
#define MROWS (Tn * Bn)          // 4096, TIME-MAJOR: row m = t*Bn + b
#define KCAT 2048
#define NMI (MROWS / 128)        // 32 M-tiles, each spans 16 time-steps
#define NTILES (NMI * (Vn / 128))   // 8000 logits tiles
#define NUTILES (NMI * (Hn / 128))  // 256 U tiles

__device__ float g_R0pre[MROWS * Dn];
__device__ float g_R1pre[MROWS * Dn];
__device__ float g_R0[MROWS * Dn];
__device__ float g_R1[MROWS * Dn];
__device__ float g_Hpre[MROWS * Hn];
__device__ float g_H[MROWS * Hn];
__device__ unsigned g_cnt[4];
__device__ unsigned g_done[4];
__device__ unsigned g_prog_r;       // rscan progress (steps completed)
__device__ unsigned g_prog;         // hscan progress
__device__ unsigned g_uctr;         // U-tile queue
__device__ unsigned g_udone[NMI];   // U-tiles completed per mi
__device__ unsigned g_tilectr;      // logits tile queue

__device__ __half g_Xcat[(size_t)MROWS * KCAT];   // [X | R0 | R1] fp16, time-major
__device__ __half g_Wcat[(size_t)Hn * KCAT];      // [W_x | U0 | U1] fp16
__device__ __half g_Win0h[(size_t)Dn * En];
__device__ __half g_Win1h[(size_t)Dn * En];
__device__ __half g_Wh[(size_t)Vn * Hn];
__device__ __half g_Hh[(size_t)MROWS * Hn];

__device__ __forceinline__ uint32_t smem_u32(const void* p) {
    uint32_t a;
    asm("{ .reg .u64 t; cvta.to.shared.u64 t, %1; cvt.u32.u64 %0, t; }" : "=r"(a) : "l"(p));
    return a;
}
__device__ __forceinline__ void cp_async16(uint32_t saddr, const void* gaddr) {
    asm volatile("cp.async.cg.shared.global [%0], [%1], 16;" :: "r"(saddr), "l"(gaddr));
}
#define CP_COMMIT() asm volatile("cp.async.commit_group;" ::: "memory")
#define CP_WAIT(N)  asm volatile("cp.async.wait_group %0;" :: "n"(N) : "memory")

__device__ __forceinline__ void ldsm_x4(uint32_t& r0, uint32_t& r1, uint32_t& r2,
                                        uint32_t& r3, uint32_t addr) {
    asm volatile("ldmatrix.sync.aligned.m8n8.x4.shared.b16 {%0,%1,%2,%3}, [%4];"
                 : "=r"(r0), "=r"(r1), "=r"(r2), "=r"(r3) : "r"(addr));
}
__device__ __forceinline__ void mma16816h(float* c, const uint32_t* a, const uint32_t* b) {
    asm volatile(
        "mma.sync.aligned.m16n8k16.row.col.f32.f16.f16.f32 "
        "{%0,%1,%2,%3}, {%4,%5,%6,%7}, {%8,%9}, {%0,%1,%2,%3};"
        : "+f"(c[0]), "+f"(c[1]), "+f"(c[2]), "+f"(c[3])
        : "r"(a[0]), "r"(a[1]), "r"(a[2]), "r"(a[3]), "r"(b[0]), "r"(b[1]));
}

// -------- launch 1: embedding gather (time-major) + counter reset -------------
__global__ void embed_h(const int* __restrict__ ids, const float* __restrict__ emb,
                        __half* __restrict__ Xcat)
{
    int blk = blockIdx.x;                 // flat ids index = b*Tn + t
    if (blk == 0 && threadIdx.x == 0) {
        g_prog_r = 0u; g_prog = 0u; g_uctr = 0u; g_tilectr = 0u;
        for (int i = 0; i < NMI; ++i) g_udone[i] = 0u;
    }
    int b = blk / Tn, t = blk % Tn;
    int m = t * Bn + b;                   // time-major row
    int id = __ldg(ids + blk);
    float4 v = __ldg(((const float4*)(emb + (size_t)id * En)) + threadIdx.x);
    __half2* dst = (__half2*)(Xcat + (size_t)m * KCAT) + threadIdx.x * 2;
    dst[0] = __floats2half2_rn(v.x, v.y);
    dst[1] = __floats2half2_rn(v.z, v.w);
}

// -------- launch 2: Win0 + Win1 -> fp16 ---------------------------------------
__global__ void cvt_win(const float* __restrict__ Win0, const float* __restrict__ Win1,
                        __half* __restrict__ W0h, __half* __restrict__ W1h)
{
    int i = blockIdx.x * blockDim.x + threadIdx.x;
    const int n4 = Dn * En / 4;
    const float* src; __half* dst; int k;
    if (i < n4) { src = Win0; dst = W0h; k = i; }
    else        { src = Win1; dst = W1h; k = i - n4; }
    float4 v = ((const float4*)src)[k];
    __half2* dp = (__half2*)dst;
    dp[k * 2 + 0] = __floats2half2_rn(v.x, v.y);
    dp[k * 2 + 1] = __floats2half2_rn(v.z, v.w);
}

// -------- launch 3: outW -> fp16  AND  pack [W_x|U0|U1] -> Wcat ---------------
#define NB_OUTW (Vn * Hn / 4 / 256)
__global__ void cvt_whpack(const float* __restrict__ outW, __half* __restrict__ Wh16,
                           const float* __restrict__ Wx, const float* __restrict__ U0,
                           const float* __restrict__ U1, __half* __restrict__ Wcat)
{
    if (blockIdx.x < NB_OUTW) {
        int i = blockIdx.x * 256 + threadIdx.x;
        float4 v = ((const float4*)outW)[i];
        __half2* dp = (__half2*)Wh16;
        dp[i * 2 + 0] = __floats2half2_rn(v.x, v.y);
        dp[i * 2 + 1] = __floats2half2_rn(v.z, v.w);
    } else {
        int n = blockIdx.x - NB_OUTW;
#pragma unroll
        for (int h = 0; h < 2; ++h) {
            int c = (threadIdx.x + h * 256) * 4;
            const float* src;
            if (c < En)            src = Wx + (size_t)n * En + c;
            else if (c < En + Dn)  src = U0 + (size_t)n * Dn + (c - En);
            else                   src = U1 + (size_t)n * Dn + (c - En - Dn);
            float4 v = *(const float4*)src;
            __half2* p = (__half2*)(Wcat + (size_t)n * KCAT + c);
            p[0] = __floats2half2_rn(v.x, v.y);
            p[1] = __floats2half2_rn(v.z, v.w);
        }
    }
}

#define KCH 64
#define TILEB (128 * KCH * 2)
#define STAGEB (2 * TILEB)

// ---- shared tile-GEMM body. flags: 1=bias, 2=accumulate, 4=time->batch row remap
__device__ __forceinline__ void gemm_tile(
    uint32_t sbase, int tid, int lane, int wm, int wn,
    const __half* gA, const __half* gB, int lda, int ldb, int K,
    const float* bias, float* C, int ldc, int m0, int n0, int flags)
{
    float acc[4][4][4];
#pragma unroll
    for (int a = 0; a < 4; a++)
#pragma unroll
        for (int bq = 0; bq < 4; bq++)
#pragma unroll
            for (int cx = 0; cx < 4; cx++) acc[a][bq][cx] = 0.f;

    auto issue_stage = [&](int s, int kc) {
        uint32_t stb = sbase + s * STAGEB;
        const __half* ga = gA + kc * KCH;
#pragma unroll
        for (int i = 0; i < 4; ++i) {
            int q = tid + i * 256;
            int r = q >> 3, c = q & 7;
            uint32_t sa = stb + ((r >> 3) << 10) + ((r & 7) << 7) + ((c ^ (r & 7)) << 4);
            cp_async16(sa, ga + (size_t)r * lda + c * 8);
        }
        const __half* gb = gB + kc * KCH;
        uint32_t tb = stb + TILEB;
#pragma unroll
        for (int i = 0; i < 4; ++i) {
            int q = tid + i * 256;
            int r = q >> 3, c = q & 7;
            uint32_t sa = tb + ((r >> 3) << 10) + ((r & 7) << 7) + ((c ^ (r & 7)) << 4);
            cp_async16(sa, gb + (size_t)r * ldb + c * 8);
        }
    };

    issue_stage(0, 0);
    CP_COMMIT();

    const int NKC = K / KCH;
    for (int kc = 0; kc < NKC; ++kc) {
        if (kc + 1 < NKC) { issue_stage((kc + 1) & 1, kc + 1); CP_COMMIT(); CP_WAIT(1); }
        else { CP_WAIT(0); }
        __syncthreads();

        uint32_t sA = sbase + (kc & 1) * STAGEB;
        uint32_t sB = sA + TILEB;

#pragma unroll
        for (int ks = 0; ks < KCH / 16; ++ks) {
            uint32_t ah[4][4], bh[4][2];
            int ra = (lane & 7) + ((lane >> 3) & 1) * 8;
            int ca = ks * 2 + ((lane >> 4) & 1);
#pragma unroll
            for (int mt = 0; mt < 4; ++mt) {
                int row = wm * 64 + mt * 16 + ra;
                uint32_t off = ((row >> 3) << 10) + ((row & 7) << 7)
                             + (((ca ^ (row & 7)) & 7) << 4);
                ldsm_x4(ah[mt][0], ah[mt][1], ah[mt][2], ah[mt][3], sA + off);
            }
            int rb = (lane & 7) + ((lane >> 4) & 1) * 8;
            int cb = ks * 2 + ((lane >> 3) & 1);
#pragma unroll
            for (int np = 0; np < 2; ++np) {
                int row = wn * 32 + np * 16 + rb;
                uint32_t off = ((row >> 3) << 10) + ((row & 7) << 7)
                             + (((cb ^ (row & 7)) & 7) << 4);
                ldsm_x4(bh[np * 2][0], bh[np * 2][1],
                        bh[np * 2 + 1][0], bh[np * 2 + 1][1], sB + off);
            }
#pragma unroll
            for (int mt = 0; mt < 4; ++mt)
#pragma unroll
                for (int nt = 0; nt < 4; ++nt)
                    mma16816h(acc[mt][nt], ah[mt], bh[nt]);
        }
        __syncthreads();
    }

#pragma unroll
    for (int mt = 0; mt < 4; ++mt) {
        int r0g = m0 + wm * 64 + mt * 16 + (lane >> 2);
        int r1g = r0g + 8;
        int row0 = (flags & 4) ? (((r0g & 7) << 9) | (r0g >> 3)) : r0g;
        int row1 = (flags & 4) ? (((r1g & 7) << 9) | (r1g >> 3)) : r1g;
#pragma unroll
        for (int nt = 0; nt < 4; ++nt) {
            int cc = n0 + wn * 32 + nt * 8 + (lane & 3) * 2;
            float bx = 0.f, by = 0.f;
            if (flags & 1) { float2 bia = *(const float2*)(bias + cc); bx = bia.x; by = bia.y; }
            float* p0 = C + (size_t)row0 * ldc + cc;
            float* p1 = C + (size_t)row1 * ldc + cc;
            float2 v0 = make_float2(acc[mt][nt][0] + bx, acc[mt][nt][1] + by);
            float2 v1 = make_float2(acc[mt][nt][2] + bx, acc[mt][nt][3] + by);
            if (flags & 2) {
                float2 o0 = *(float2*)p0, o1 = *(float2*)p1;
                v0.x += o0.x; v0.y += o0.y; v1.x += o1.x; v1.y += o1.y;
            }
            *(float2*)p0 = v0;
            *(float2*)p1 = v1;
        }
    }
}

// -------- launches 4,5: standalone GEMMs --------------------------------------
__global__ void __launch_bounds__(256, 2)
gemm16(const __half* __restrict__ A, const __half* __restrict__ W,
       const float* __restrict__ bias, float* __restrict__ C,
       const __half* __restrict__ W1, float* __restrict__ C1,
       int N, int K, int lda, int ldb, int flags)
{
    extern __shared__ __align__(16) char sm[];
    uint32_t sbase = smem_u32(sm);
    if (blockIdx.z) { W = W1; C = C1; }
    int tid = threadIdx.x, lane = tid & 31, wid = tid >> 5;
    gemm_tile(sbase, tid, lane, wid >> 2, wid & 3,
              A + (size_t)blockIdx.x * 128 * lda, W + (size_t)blockIdx.y * 128 * ldb,
              lda, ldb, K, bias, C, N, blockIdx.x * 128, blockIdx.y * 128, flags);
}

__device__ __forceinline__ void gbar_arrive_wait(unsigned* cnt, unsigned target)
{
    if (threadIdx.x == 0) {
        __threadfence();
        atomicAdd(cnt, 1u);
        while (*(volatile unsigned*)cnt < target) __nanosleep(32);
        __threadfence();
    }
    __syncthreads();
}
__device__ __forceinline__ void gbar_reset(unsigned* cnt, unsigned* done, unsigned nctas)
{
    if (threadIdx.x == 0) {
        unsigned v = atomicAdd(done, 1u);
        if (v == nctas - 1u) { *done = 0u; *cnt = 0u; __threadfence(); }
    }
}

// -------- launch 6: mega-kernel (time-major fine-grained pipeline) ------------
//   bid   0-127: rscan; publishes g_prog_r per step
//   bid 128-255: hscan; per-t gate on g_udone[t>>4]; publishes g_prog
//   bid 256-295: U-GEMM workers (Hpre += [R0|R1]@[U0|U1]^T), gate 16*(mi+1)
// All drain into logits queue (gate g_prog >= 16*(mi+1)), epilogue remaps rows.
__global__ void __launch_bounds__(256, 2)
crsd_mega(const float* __restrict__ pre0, const float* __restrict__ pre1,
          const float* __restrict__ Wr0, const float* __restrict__ Wr1,
          float* __restrict__ R0, float* __restrict__ R1,
          __half* __restrict__ Xcat, const __half* __restrict__ Wcat,
          const float* __restrict__ Hpre_c, float* __restrict__ Hpre,
          const float* __restrict__ Whw,
          float* __restrict__ Hout, __half* __restrict__ Hh,
          const __half* __restrict__ Wlg, const float* __restrict__ bias,
          float* __restrict__ C)
{
    extern __shared__ __align__(16) char sm[];
    int bid = blockIdx.x;
    int tid = threadIdx.x, lane = tid & 31, wid = tid >> 5;

    if (bid < 128) {
        // ===================== rscan =====================
        float* smem = (float*)sm;
        float* sW = smem;                 // 8*512
        float* sR = smem + 8 * Dn;        // 8*512 ([b][d], rows contiguous at fixed t)
        int res  = bid >> 6;
        int jblk = bid & 63;
        int j0   = jblk * 8;
        const float* pre  = res ? pre1 : pre0;
        const float* Wres = res ? Wr1 : Wr0;
        float* Rout = res ? R1 : R0;
        int b = tid >> 5;

        for (int i = tid; i < 8 * Dn / 4; i += 256)
            ((float4*)sW)[i] = ((const float4*)(Wres + (size_t)j0 * Dn))[i];
        __syncthreads();

        for (int t = 0; t < Tn; ++t) {
            if (t == 0) {
                float4 z = make_float4(0.f, 0.f, 0.f, 0.f);
                for (int i = tid; i < Bn * Dn / 4; i += 256) ((float4*)sR)[i] = z;
            } else {
                const float4* src = (const float4*)(Rout + (size_t)(t - 1) * Bn * Dn);
                for (int i = tid; i < Bn * Dn / 4; i += 256)
                    ((float4*)sR)[i] = __ldcg(src + i);
            }
            __syncthreads();

            const float4* rb = (const float4*)(sR + b * Dn);
            float4 rv[4];
#pragma unroll
            for (int i = 0; i < 4; i++) rv[i] = rb[i * 32 + lane];

            float myout = 0.f;
#pragma unroll
            for (int jj = 0; jj < 8; ++jj) {
                const float4* wr = (const float4*)(sW + jj * Dn);
                float sv = 0.f;
#pragma unroll
                for (int i = 0; i < 4; i++) {
                    float4 w4 = wr[i * 32 + lane];
                    sv += rv[i].x * w4.x + rv[i].y * w4.y + rv[i].z * w4.z + rv[i].w * w4.w;
                }
#pragma unroll
                for (int off = 16; off; off >>= 1) sv += __shfl_xor_sync(0xffffffffu, sv, off);
                if (lane == jj) myout = sv;
            }
            if (lane < 8) {
                int j = j0 + lane;
                size_t row = (size_t)t * Bn + b;      // time-major
                float rold = sR[b * Dn + j];
                float p = __ldcg(pre + row * Dn + j);
                float val = 0.5f * rold + 0.5f * tanhf(p + myout);
                Rout[row * Dn + j] = val;
                Xcat[row * KCAT + En + res * Dn + j] = __float2half(val);
            }
            __syncthreads();
            gbar_arrive_wait(&g_cnt[0], 128u * (unsigned)(t + 1));
            if (bid == 0 && tid == 0)
                *(volatile unsigned*)&g_prog_r = (unsigned)(t + 1);
        }
        gbar_reset(&g_cnt[0], &g_done[0], 128u);
        __syncthreads();

    } else if (bid < 256) {
        // ===================== hscan =====================
        float* smem = (float*)sm;
        float* sW = smem;                  // 8*1024
        float* sH = smem + 8 * Hn;         // 8*1024
        int hbid = bid - 128;
        int j0 = hbid * 8;
        int b = tid >> 5;

        for (int i = tid; i < 8 * Hn / 4; i += 256)
            ((float4*)sW)[i] = ((const float4*)(Whw + (size_t)j0 * Hn))[i];
        __syncthreads();

        for (int t = 0; t < Tn; ++t) {
            if ((t & 15) == 0) {           // gate on this 16-step slab's U tiles
                if (tid == 0) {
                    int mi = t >> 4;
                    while (*(volatile unsigned*)&g_udone[mi] < 8u) __nanosleep(128);
                    __threadfence();
                }
                __syncthreads();
            }
            if (t == 0) {
                float4 z = make_float4(0.f, 0.f, 0.f, 0.f);
                for (int i = tid; i < Bn * Hn / 4; i += 256) ((float4*)sH)[i] = z;
            } else {
                const float4* src = (const float4*)(Hout + (size_t)(t - 1) * Bn * Hn);
                for (int i = tid; i < Bn * Hn / 4; i += 256)
                    ((float4*)sH)[i] = __ldcg(src + i);
            }
            __syncthreads();

            const float4* hb = (const float4*)(sH + b * Hn);
            float4 hv[8];
#pragma unroll
            for (int i = 0; i < 8; i++) hv[i] = hb[i * 32 + lane];

            float myout = 0.f;
#pragma unroll
            for (int jj = 0; jj < 8; ++jj) {
                const float4* wr = (const float4*)(sW + jj * Hn);
                float sv = 0.f;
#pragma unroll
                for (int i = 0; i < 8; i++) {
                    float4 w4 = wr[i * 32 + lane];
                    sv += hv[i].x * w4.x + hv[i].y * w4.y + hv[i].z * w4.z + hv[i].w * w4.w;
                }
#pragma unroll
                for (int off = 16; off; off >>= 1) sv += __shfl_xor_sync(0xffffffffu, sv, off);
                if (lane == jj) myout = sv;
            }
            if (lane < 8) {
                int j = j0 + lane;
                size_t row = (size_t)t * Bn + b;      // time-major
                float val = tanhf(__ldcg(Hpre_c + row * Hn + j) + myout);
                Hout[row * Hn + j] = val;
                Hh[row * Hn + j] = __float2half(val);
            }
            __syncthreads();
            gbar_arrive_wait(&g_cnt[2], 128u * (unsigned)(t + 1));
            if (hbid == 0 && tid == 0)
                *(volatile unsigned*)&g_prog = (unsigned)(t + 1);
        }
        gbar_reset(&g_cnt[2], &g_done[2], 128u);
        __syncthreads();

    } else {
        // ===================== U-GEMM workers =====================
        uint32_t sbase = smem_u32(sm);
        int wm = wid >> 2, wn = wid & 3;
        __shared__ unsigned s_ut;
        for (;;) {
            if (tid == 0) s_ut = atomicAdd(&g_uctr, 1u);
            __syncthreads();
            unsigned q = s_ut;
            __syncthreads();
            if (q >= NUTILES) break;
            int mi = q >> 3;          // 0..31, time-slab order
            int ni = q & 7;
            if (tid == 0) {
                unsigned need = (unsigned)(mi + 1) * 16u;
                while (*(volatile unsigned*)&g_prog_r < need) __nanosleep(128);
            }
            __syncthreads();
            __threadfence();
            gemm_tile(sbase, tid, lane, wm, wn,
                      Xcat + En + (size_t)mi * 128 * KCAT,
                      Wcat + En + (size_t)ni * 128 * KCAT,
                      KCAT, KCAT, 1024, nullptr, Hpre, Hn,
                      mi * 128, ni * 128, 2);
            __threadfence();
            if (tid == 0) atomicAdd(&g_udone[mi], 1u);
            __syncthreads();
        }
    }

    // ===================== logits workers (all CTAs) =====================
    uint32_t sbase = smem_u32(sm);
    int wm = wid >> 2, wn = wid & 3;
    __shared__ unsigned s_tile;
    for (;;) {
        if (tid == 0) s_tile = atomicAdd(&g_tilectr, 1u);
        __syncthreads();
        unsigned tile = s_tile;
        __syncthreads();
        if (tile >= NTILES) break;

        int mi = tile / 250;          // time-slab order
        int ni = tile % 250;

        if (tid == 0) {
            unsigned need = (unsigned)(mi + 1) * 16u;
            while (*(volatile unsigned*)&g_prog < need) __nanosleep(128);
        }
        __syncthreads();
        __threadfence();

        gemm_tile(sbase, tid, lane, wm, wn,
                  Hh + (size_t)mi * 128 * Hn, Wlg + (size_t)ni * 128 * Hn,
                  Hn, Hn, Hn, bias, C, Vn, mi * 128, ni * 128, 1 | 4);
    }
}

extern "C" void kernel_launch(void* const* d_in, const int* in_sizes, int n_in,
                              void* d_out, int out_size)
{
    const int*   ids   = (const int*)  d_in[0];
    const float* emb   = (const float*)d_in[1];
    const float* W_x   = (const float*)d_in[2];
    const float* W_h   = (const float*)d_in[3];
    const float* b_h   = (const float*)d_in[4];
    const float* Win0  = (const float*)d_in[5];
    const float* Wres0 = (const float*)d_in[6];
    const float* U0    = (const float*)d_in[7];
    const float* Win1  = (const float*)d_in[8];
    const float* Wres1 = (const float*)d_in[9];
    const float* U1    = (const float*)d_in[10];
    const float* outW  = (const float*)d_in[11];
    const float* outb  = (const float*)d_in[12];
    float* out = (float*)d_out;

    float *R0pre, *R1pre, *R0, *R1, *Hpre, *Hst;
    __half *Xcat, *Wcat, *Win0h, *Win1h, *Wh16, *Hh16;
    cudaGetSymbolAddress((void**)&R0pre, g_R0pre);
    cudaGetSymbolAddress((void**)&R1pre, g_R1pre);
    cudaGetSymbolAddress((void**)&R0,    g_R0);
    cudaGetSymbolAddress((void**)&R1,    g_R1);
    cudaGetSymbolAddress((void**)&Hpre,  g_Hpre);
    cudaGetSymbolAddress((void**)&Hst,   g_H);
    cudaGetSymbolAddress((void**)&Xcat,  g_Xcat);
    cudaGetSymbolAddress((void**)&Wcat,  g_Wcat);
    cudaGetSymbolAddress((void**)&Win0h, g_Win0h);
    cudaGetSymbolAddress((void**)&Win1h, g_Win1h);
    cudaGetSymbolAddress((void**)&Wh16,  g_Wh);
    cudaGetSymbolAddress((void**)&Hh16,  g_Hh);

    cudaFuncSetAttribute(gemm16,
                         cudaFuncAttributeMaxDynamicSharedMemorySize, 2 * STAGEB);
    cudaFuncSetAttribute(crsd_mega,
                         cudaFuncAttributeMaxDynamicSharedMemorySize, 2 * STAGEB);

    // (1) embedding gather (time-major) + counter reset
    embed_h<<<MROWS, 256>>>(ids, emb, Xcat);

    // (2) Win0/Win1 -> fp16
    cvt_win<<<2 * (Dn * En / 4) / 256, 256>>>(Win0, Win1, Win0h, Win1h);

    // (3) outW -> fp16  +  pack [W_x|U0|U1] -> Wcat
    cvt_whpack<<<NB_OUTW + Hn, 256>>>(outW, Wh16, W_x, U0, U1, Wcat);

    // (4) reservoir input projections (dual via z), K=1024 over Xcat x-part
    gemm16<<<dim3(MROWS / 128, Dn / 128, 2), 256, 2 * STAGEB>>>(
        Xcat, Win0h, nullptr, R0pre, Win1h, R1pre, Dn, En, KCAT, En, 0);

    // (5) Hpre_x = X @ W_x^T + b_h
    gemm16<<<dim3(MROWS / 128, Hn / 128, 1), 256, 2 * STAGEB>>>(
        Xcat, Wcat, b_h, Hpre, nullptr, nullptr, Hn, En, KCAT, KCAT, 1);

    // (6) mega-kernel: rscan || U-GEMM || hscan || logits, 16-step granularity
    crsd_mega<<<296, 256, 2 * STAGEB>>>(
        R0pre, R1pre, Wres0, Wres1, R0, R1, Xcat, Wcat,
        Hpre, Hpre, W_h, Hst, Hh16, Wh16, outb, out);
}